// round 17
// baseline (speedup 1.0000x reference)
#include <cuda_runtime.h>
#include <cuda_fp16.h>
#include <cstdint>

// ---------------- problem constants (pinned by the dataset) ----------------
#define B_    32768
#define H_    512
#define MD_   8
#define CD_   1024
#define KIN   532          // H + 20
#define KP    544          // KIN padded to 17 * 32
#define NCAT_ 262144
#define EPS_  1e-6f

// ---------------- scratch (static device allocations only) -----------------
__device__ int   g_rowptr[B_ + 1];                        // CSR row pointers into cat_*
__device__ float g_bias[B_ * 6];
__device__ __align__(128) __half g_xn[(size_t)B_ * KP];   // LN1 out, fp16, k-permuted
__device__ __align__(128) __half g_w1p[CD_ * KP];         // mlp1_w fp16, k-permuted
__device__ __align__(128) float g_acc[(size_t)B_ * 8];    // per-row {p[6], sum, sumsq}
__device__ float g_wp[6 * CD_];                           // out_w * ln2_g
__device__ float g_S[6];                                  // row sums of g_wp
__device__ float g_T[6];                                  // out_w @ ln2_b

// k-permutation within each 16-half group: dest 4-half block r (g=r>>2,t=r&3)
// holds source halves {p, p+1, p+8, p+9} with p = 16g + 2t.

// ---------------- PTX helpers (baseline ISA only, no 'a' features) ---------
__device__ __forceinline__ uint32_t smem_u32(const void* p) {
    uint32_t a;
    asm("{ .reg .u64 t; cvta.to.shared.u64 t, %1; cvt.u32.u64 %0, t; }" : "=r"(a) : "l"(p));
    return a;
}
__device__ __forceinline__ void cp_async16(uint32_t saddr, const void* gaddr) {
    asm volatile("cp.async.cg.shared.global [%0], [%1], 16;" :: "r"(saddr), "l"(gaddr));
}
__device__ __forceinline__ void cp_commit() {
    asm volatile("cp.async.commit_group;");
}
template <int N>
__device__ __forceinline__ void cp_wait() {
    asm volatile("cp.async.wait_group %0;" :: "n"(N) : "memory");
}
__device__ __forceinline__ void mma_f16(float* c, const uint32_t* a, const uint32_t* b) {
    asm volatile(
        "mma.sync.aligned.m16n8k16.row.col.f32.f16.f16.f32 "
        "{%0,%1,%2,%3}, {%4,%5,%6,%7}, {%8,%9}, {%0,%1,%2,%3};"
        : "+f"(c[0]), "+f"(c[1]), "+f"(c[2]), "+f"(c[3])
        : "r"(a[0]), "r"(a[1]), "r"(a[2]), "r"(a[3]), "r"(b[0]), "r"(b[1]));
}
__device__ __forceinline__ uint32_t pack2h(float a, float b) {
    __half2 h = __floats2half2_rn(a, b);
    return *(uint32_t*)&h;
}

// ---------------- kernel A: fused prologue (zero | w1pad | prep | rowptr) --
//   [0, ZBLK)                 : zero g_acc (grid-stride)
//   [ZBLK, ZBLK+WBLK)         : w1 pad + fp16 + k-permute
//   [ZBLK+WBLK, +6)           : prep (W', S, T)
//   [ZBLK+WBLK+6, +RBLK)      : CSR row pointers from sorted cat_seg
#define ZBLK 64
#define WBLK ((CD_ * KP / 4 + 255) / 256)    // 544
#define RBLK (NCAT_ / 256)                   // 1024
__global__ __launch_bounds__(256) void prologue_kernel(const float* __restrict__ w1,
                                                       const float* __restrict__ out_w,
                                                       const float* __restrict__ ln2g,
                                                       const float* __restrict__ ln2b,
                                                       const int* __restrict__ cat_seg) {
    int blk = blockIdx.x;
    int tid = threadIdx.x;
    if (blk < ZBLK) {
        int i = blk * 256 + tid;
        int stride = ZBLK * 256;
        for (int j = i; j < B_ * 8; j += stride) g_acc[j] = 0.f;
    } else if (blk < ZBLK + WBLK) {
        int bi = (blk - ZBLK) * 256 + tid;        // dest 4-half block
        if (bi < CD_ * KP / 4) {
            int n = bi / (KP / 4);
            int r = bi % (KP / 4);
            int g = r >> 2, t = r & 3;
            int p = g * 16 + t * 2;
            const float* wrow = w1 + (size_t)n * KIN;
            float v0 = (p + 0 < KIN) ? wrow[p + 0] : 0.f;
            float v1 = (p + 1 < KIN) ? wrow[p + 1] : 0.f;
            float v2 = (p + 8 < KIN) ? wrow[p + 8] : 0.f;
            float v3 = (p + 9 < KIN) ? wrow[p + 9] : 0.f;
            uint2 u;
            u.x = pack2h(v0, v1);
            u.y = pack2h(v2, v3);
            ((uint2*)g_w1p)[bi] = u;
        }
    } else if (blk < ZBLK + WBLK + 6) {
        int c = blk - ZBLK - WBLK;                // 0..5
        int lane = tid & 31, wid = tid >> 5;
        float s = 0.f, t = 0.f;
        for (int k = tid; k < CD_; k += 256) {
            float w  = out_w[c * CD_ + k];
            float wp = w * ln2g[k];
            g_wp[c * CD_ + k] = wp;
            s += wp;
            t += w * ln2b[k];
        }
        #pragma unroll
        for (int o = 16; o > 0; o >>= 1) {
            s += __shfl_down_sync(0xffffffffu, s, o);
            t += __shfl_down_sync(0xffffffffu, t, o);
        }
        __shared__ float rs[8], rt[8];
        if (lane == 0) { rs[wid] = s; rt[wid] = t; }
        __syncthreads();
        if (tid == 0) {
            float S = 0.f, T = 0.f;
            #pragma unroll
            for (int w = 0; w < 8; w++) { S += rs[w]; T += rt[w]; }
            g_S[c] = S; g_T[c] = T;
        }
    } else {
        int i = (blk - ZBLK - WBLK - 6) * 256 + tid;
        if (i < NCAT_) {
            int s = cat_seg[i];
            if (i == 0) {
                for (int b = 0; b <= s; b++) g_rowptr[b] = 0;
            } else {
                int sp = cat_seg[i - 1];
                for (int b = sp + 1; b <= s; b++) g_rowptr[b] = i;
            }
            if (i == NCAT_ - 1) {
                for (int b = s + 1; b <= B_; b++) g_rowptr[b] = NCAT_;
            }
        }
    }
}

// ---------------- kernel B: fused segment-mean + meta conv + bias + LN1 ----
// warp per row, barrier-free. Contiguous CSR gather replaces atomics.
__global__ __launch_bounds__(256) void ln1meta_kernel(const float* __restrict__ encode,
                                                      const float* __restrict__ table,
                                                      const float* __restrict__ credit,
                                                      const float* __restrict__ conv_w,
                                                      const float* __restrict__ conv_b,
                                                      const int* __restrict__ meta_ids,
                                                      const int* __restrict__ cat_ids,
                                                      const float* __restrict__ g1,
                                                      const float* __restrict__ b1) {
    int lane = threadIdx.x & 31;
    int row = blockIdx.x * 8 + (threadIdx.x >> 5);

    // ---- segment mean over contiguous entries [s0, s1) ----
    int s0 = g_rowptr[row], s1 = g_rowptr[row + 1];
    float a8[8];
    #pragma unroll
    for (int d = 0; d < 8; d++) a8[d] = 0.f;
    for (int e = s0 + lane; e < s1; e += 32) {
        const float4* t4 = (const float4*)(table + (size_t)cat_ids[e] * MD_);
        float4 a = t4[0], b = t4[1];
        a8[0] += a.x; a8[1] += a.y; a8[2] += a.z; a8[3] += a.w;
        a8[4] += b.x; a8[5] += b.y; a8[6] += b.z; a8[7] += b.w;
    }
    #pragma unroll
    for (int d = 0; d < 8; d++) {
        #pragma unroll
        for (int o = 16; o > 0; o >>= 1)
            a8[d] += __shfl_xor_sync(0xffffffffu, a8[d], o);
    }
    float inv = 1.0f / fmaxf((float)(s1 - s0), 1.0f);

    // ---- build mat[6][8] (all lanes; meta rows broadcast via L1) ----
    float mat[6][8];
    #pragma unroll
    for (int d = 0; d < 8; d++) mat[0][d] = a8[d] * inv;
    #pragma unroll
    for (int j = 0; j < 5; j++) {
        int id = meta_ids[row * 5 + j];
        const float4* t4 = (const float4*)(table + (size_t)id * MD_);
        float4 a = t4[0], b = t4[1];
        mat[j + 1][0] = a.x; mat[j + 1][1] = a.y; mat[j + 1][2] = a.z; mat[j + 1][3] = a.w;
        mat[j + 1][4] = b.x; mat[j + 1][5] = b.y; mat[j + 1][6] = b.z; mat[j + 1][7] = b.w;
    }

    // ---- conv+relu+maxpool: lane < 20 computes pooled output (c, t0) ----
    float mv = 0.f;
    if (lane < 20) {
        int c = lane >> 2, t0 = lane & 3;
        float cb = conv_b[c];
        float p0 = -1e30f;
        #pragma unroll
        for (int dt = 0; dt < 3; dt++) {
            int t = t0 + dt;
            float s = cb;
            #pragma unroll
            for (int i = 0; i < 6; i++)
                #pragma unroll
                for (int k = 0; k < 3; k++)
                    s += conv_w[c * 18 + i * 3 + k] * mat[i][t + k];
            p0 = fmaxf(p0, fmaxf(s, 0.f));
        }
        mv = p0;
    }

    // ---- credit bias (lanes 0..5) ----
    if (lane < 6) {
        float s = 0.f;
        #pragma unroll
        for (int c = 0; c < 6; c++) s += credit[row * 6 + c];
        float me = credit[row * 6 + lane];
        g_bias[row * 6 + lane] = (s > 0.f) ? me / s : (1.0f / 6.0f);
    }

    // ---- LN1 over concat(encode_row, mv[0..19]) ----
    const float4* erow = (const float4*)(encode + (size_t)row * H_);
    float4 xv[4];
    #pragma unroll
    for (int i = 0; i < 4; i++) xv[i] = erow[lane + 32 * i];

    float s = mv, sq = mv * mv;
    #pragma unroll
    for (int i = 0; i < 4; i++) {
        s  += xv[i].x + xv[i].y + xv[i].z + xv[i].w;
        sq += xv[i].x * xv[i].x + xv[i].y * xv[i].y
            + xv[i].z * xv[i].z + xv[i].w * xv[i].w;
    }
    #pragma unroll
    for (int o = 16; o > 0; o >>= 1) {
        s  += __shfl_xor_sync(0xffffffffu, s, o);
        sq += __shfl_xor_sync(0xffffffffu, sq, o);
    }
    float mean = s / (float)KIN;
    float var  = sq / (float)KIN - mean * mean;
    float rstd = rsqrtf(var + EPS_);

    uint2* xo = (uint2*)(g_xn + (size_t)row * KP);

    #pragma unroll
    for (int i = 0; i < 4; i++) {
        int j = lane + 32 * i;                 // src 4-half block
        float4 gg = ((const float4*)g1)[j];
        float4 bb = ((const float4*)b1)[j];
        float v0 = (xv[i].x - mean) * rstd * gg.x + bb.x;
        float v1 = (xv[i].y - mean) * rstd * gg.y + bb.y;
        float v2 = (xv[i].z - mean) * rstd * gg.z + bb.z;
        float v3 = (xv[i].w - mean) * rstd * gg.w + bb.w;
        uint32_t u0 = pack2h(v0, v1);
        uint32_t u1 = pack2h(v2, v3);
        uint32_t pu0 = __shfl_xor_sync(0xffffffffu, u0, 2);
        uint32_t pu1 = __shfl_xor_sync(0xffffffffu, u1, 2);
        int g = j >> 2, t = j & 3;
        uint2 u; int bi;
        if (t < 2) { u.x = u0;  u.y = pu0; bi = g * 4 + 2 * t; }
        else       { u.x = pu1; u.y = u1;  bi = g * 4 + 2 * t - 3; }
        xo[bi] = u;
    }

    // tail: dest blocks 128..135 cover src halves 512..543 (meta 20 + pad 12)
    {
        int l7 = lane & 7;
        int sbase = 16 * (l7 >> 2) + 2 * (l7 & 3);
        int s0i = sbase, s1i = sbase + 1, s2i = sbase + 8, s3i = sbase + 9;
        float m0 = __shfl_sync(0xffffffffu, mv, s0i & 31);
        float m1 = __shfl_sync(0xffffffffu, mv, s1i & 31);
        float m2 = __shfl_sync(0xffffffffu, mv, s2i & 31);
        float m3 = __shfl_sync(0xffffffffu, mv, s3i & 31);
        if (lane < 8) {
            float t0 = (s0i < 20) ? (m0 - mean) * rstd * g1[H_ + s0i] + b1[H_ + s0i] : 0.f;
            float t1 = (s1i < 20) ? (m1 - mean) * rstd * g1[H_ + s1i] + b1[H_ + s1i] : 0.f;
            float t2 = (s2i < 20) ? (m2 - mean) * rstd * g1[H_ + s2i] + b1[H_ + s2i] : 0.f;
            float t3 = (s3i < 20) ? (m3 - mean) * rstd * g1[H_ + s3i] + b1[H_ + s3i] : 0.f;
            uint2 ut;
            ut.x = pack2h(t0, t1);
            ut.y = pack2h(t2, t3);
            xo[128 + lane] = ut;
        }
    }
}

// ---------------- kernel 5: fp16 mma.sync GEMM1 + fused LN2 partials -------
// CTA tile 128x128, BK=32 halves, 8 warps 4(m)x2(n), warp tile 32x64.
// 4-stage cp.async pipeline, 2 CTAs/SM for cross-CTA latency hiding.
#define BK      32
#define SROW    48                     // halves per smem row (96 B)
#define A_HALFS (128 * SROW)
#define STG_HLF (2 * A_HALFS)          // A + B per stage (24576 B)
#define NSTG    4
#define NCHUNK  17

extern __shared__ __align__(128) __half smem_h[];

__device__ __forceinline__ void load_chunk_h(uint32_t sbase, int st, int c,
                                             int m0, int n0, int tid) {
    uint32_t a_s = sbase + st * (STG_HLF * 2);
    uint32_t b_s = a_s + A_HALFS * 2;
    const __half* Ag = g_xn  + (size_t)m0 * KP + c * BK;
    const __half* Bg = g_w1p + (size_t)n0 * KP + c * BK;
    #pragma unroll
    for (int t = 0; t < 2; t++) {
        int u = tid + t * 256;
        int row = u >> 2, seg = u & 3;          // 16B (8-half) segments
        cp_async16(a_s + (row * SROW + seg * 8) * 2, Ag + (size_t)row * KP + seg * 8);
    }
    #pragma unroll
    for (int t = 0; t < 2; t++) {
        int u = tid + t * 256;
        int row = u >> 2, seg = u & 3;
        cp_async16(b_s + (row * SROW + seg * 8) * 2, Bg + (size_t)row * KP + seg * 8);
    }
    cp_commit();
}

__global__ __launch_bounds__(256, 2) void gemm1_mma_kernel(const float* __restrict__ b1) {
    const int tid  = threadIdx.x;
    const int warp = tid >> 5;
    const int lane = tid & 31;
    const int gid  = lane >> 2;          // 0..7
    const int tig  = lane & 3;           // 0..3
    const int wm   = warp >> 1;          // 0..3  (m)
    const int wn   = warp & 1;           // 0..1  (n)
    const int n0   = blockIdx.x * 128;
    const int m0   = blockIdx.y * 128;
    uint32_t sbase = smem_u32(smem_h);

    float acc[2][8][4];
    #pragma unroll
    for (int mt = 0; mt < 2; mt++)
        #pragma unroll
        for (int nt = 0; nt < 8; nt++)
            #pragma unroll
            for (int r = 0; r < 4; r++) acc[mt][nt][r] = 0.f;

    load_chunk_h(sbase, 0, 0, m0, n0, tid);
    load_chunk_h(sbase, 1, 1, m0, n0, tid);
    load_chunk_h(sbase, 2, 2, m0, n0, tid);

    for (int c = 0; c < NCHUNK; c++) {
        if (c + 3 < NCHUNK) {
            load_chunk_h(sbase, (c + 3) & (NSTG - 1), c + 3, m0, n0, tid);
            cp_wait<3>();
        } else if (c + 2 < NCHUNK) {
            cp_wait<2>();
        } else if (c + 1 < NCHUNK) {
            cp_wait<1>();
        } else {
            cp_wait<0>();
        }
        __syncthreads();

        const __half* As = smem_h + (c & (NSTG - 1)) * STG_HLF;
        const __half* Bs = As + A_HALFS;
        const __half* Arow0 = As + (wm * 32 + gid) * SROW + tig * 4;
        const __half* Brow0 = Bs + (wn * 64 + gid) * SROW + tig * 4;

        #pragma unroll
        for (int ks = 0; ks < 2; ks++) {
            const int k = ks * 16;
            uint32_t af[2][4], bf[8][2];
            #pragma unroll
            for (int mt = 0; mt < 2; mt++) {
                uint2 q0 = *(const uint2*)(Arow0 + mt * 16 * SROW + k);
                uint2 q1 = *(const uint2*)(Arow0 + (mt * 16 + 8) * SROW + k);
                af[mt][0] = q0.x; af[mt][1] = q1.x;
                af[mt][2] = q0.y; af[mt][3] = q1.y;
            }
            #pragma unroll
            for (int nt = 0; nt < 8; nt++) {
                uint2 qb = *(const uint2*)(Brow0 + nt * 8 * SROW + k);
                bf[nt][0] = qb.x; bf[nt][1] = qb.y;
            }
            #pragma unroll
            for (int mt = 0; mt < 2; mt++)
                #pragma unroll
                for (int nt = 0; nt < 8; nt++)
                    mma_f16(acc[mt][nt], af[mt], bf[nt]);
        }
        __syncthreads();
    }

    // ---- fused epilogue: relu + per-row LN2/out-GEMM partials ----
    float part[4][8];
    #pragma unroll
    for (int pi = 0; pi < 4; pi++)
        #pragma unroll
        for (int j = 0; j < 8; j++) part[pi][j] = 0.f;

    #pragma unroll
    for (int nt = 0; nt < 8; nt++) {
        int col = n0 + wn * 64 + nt * 8 + tig * 2;
        float bl0 = __ldg(b1 + col);
        float bl1 = __ldg(b1 + col + 1);
        float w0[6], w1[6];
        #pragma unroll
        for (int c6 = 0; c6 < 6; c6++) {
            w0[c6] = __ldg(g_wp + c6 * CD_ + col);
            w1[c6] = __ldg(g_wp + c6 * CD_ + col + 1);
        }
        #pragma unroll
        for (int mt = 0; mt < 2; mt++) {
            #pragma unroll
            for (int pr = 0; pr < 2; pr++) {
                float v0 = fmaxf(acc[mt][nt][pr * 2 + 0] + bl0, 0.f);
                float v1 = fmaxf(acc[mt][nt][pr * 2 + 1] + bl1, 0.f);
                int pi = mt * 2 + pr;
                part[pi][6] += v0 + v1;
                part[pi][7] += v0 * v0 + v1 * v1;
                #pragma unroll
                for (int c6 = 0; c6 < 6; c6++)
                    part[pi][c6] += v0 * w0[c6] + v1 * w1[c6];
            }
        }
    }

    #pragma unroll
    for (int pi = 0; pi < 4; pi++)
        #pragma unroll
        for (int j = 0; j < 8; j++) {
            part[pi][j] += __shfl_xor_sync(0xffffffffu, part[pi][j], 1);
            part[pi][j] += __shfl_xor_sync(0xffffffffu, part[pi][j], 2);
        }

    if (tig == 0) {
        #pragma unroll
        for (int pi = 0; pi < 4; pi++) {
            int mt = pi >> 1, pr = pi & 1;
            int row = m0 + wm * 32 + mt * 16 + pr * 8 + gid;
            float* dst = g_acc + (size_t)row * 8;
            #pragma unroll
            for (int j = 0; j < 8; j++) atomicAdd(dst + j, part[pi][j]);
        }
    }
}

// ---------------- kernel 6: tiny finalize: LN2 stats + affine + biases -----
__global__ __launch_bounds__(256) void final2_kernel(const float* __restrict__ out_b,
                                                     float* __restrict__ out) {
    int i = blockIdx.x * blockDim.x + threadIdx.x;   // B*6
    if (i >= B_ * 6) return;
    int row = i / 6, c = i % 6;
    const float* a = g_acc + (size_t)row * 8;
    float p = a[c], s = a[6], q = a[7];
    float mu   = s * (1.0f / (float)CD_);
    float var  = q * (1.0f / (float)CD_) - mu * mu;
    float rstd = rsqrtf(var + EPS_);
    out[i] = rstd * p - rstd * mu * g_S[c] + g_T[c] + out_b[c] + g_bias[i];
}

// ---------------- launch ---------------------------------------------------
extern "C" void kernel_launch(void* const* d_in, const int* in_sizes, int n_in,
                              void* d_out, int out_size) {
    const float* encode     = (const float*)d_in[0];
    const float* credit_vec = (const float*)d_in[1];
    const float* meta_table = (const float*)d_in[2];
    const float* conv_w     = (const float*)d_in[3];
    const float* conv_b     = (const float*)d_in[4];
    const float* ln1_g      = (const float*)d_in[5];
    const float* ln1_b      = (const float*)d_in[6];
    const float* mlp1_w     = (const float*)d_in[7];
    const float* mlp1_b     = (const float*)d_in[8];
    const float* ln2_g      = (const float*)d_in[9];
    const float* ln2_b      = (const float*)d_in[10];
    const float* out_w      = (const float*)d_in[11];
    const float* out_b      = (const float*)d_in[12];
    const int*   meta_ids   = (const int*)d_in[13];
    const int*   cat_ids    = (const int*)d_in[14];
    const int*   cat_seg    = (const int*)d_in[15];
    float*       out        = (float*)d_out;

    const int smem_bytes = NSTG * STG_HLF * 2;   // 98304 B
    cudaFuncSetAttribute(gemm1_mma_kernel,
                         cudaFuncAttributeMaxDynamicSharedMemorySize, smem_bytes);

    prologue_kernel<<<ZBLK + WBLK + 6 + RBLK, 256>>>(mlp1_w, out_w, ln2_g, ln2_b, cat_seg);
    ln1meta_kernel<<<B_ / 8, 256>>>(encode, meta_table, credit_vec,
                                    conv_w, conv_b, meta_ids, cat_ids, ln1_g, ln1_b);
    {
        dim3 grid(CD_ / 128, B_ / 128);
        gemm1_mma_kernel<<<grid, 256, smem_bytes>>>(mlp1_b);
    }
    final2_kernel<<<(B_ * 6 + 255) / 256, 256>>>(out_b, out);
}